// round 17
// baseline (speedup 1.0000x reference)
#include <cuda_runtime.h>
#include <math.h>

#define NN 10000
#define EMAX 320000
#define ETMAX (EMAX + NN)

// ---------------- scratch (device globals; no allocation allowed) ----------------
__device__ __align__(16) float g_hbuf[NN * 1024];
__device__ __align__(16) float g_out1[NN * 256];
__device__ __align__(16) float g_out2[NN * 128];
__device__ __align__(16) float g_zb  [NN * 64];
__device__ __align__(16) float g_d1b [NN * 128];
__device__ __align__(16) float g_d2b [NN * 256];
__device__ __align__(16) float g_al  [NN * 4];
__device__ __align__(16) float g_ar  [NN * 4];
__device__ float g_sq  [NN];
__device__ int   g_cnt [NN];
__device__ int   g_off [NN + 1];
__device__ int   g_perm[ETMAX];

#define PDS 40   // smem row stride (floats): 16 k * 2 (hi,lo) + 8 pad

__device__ __forceinline__ void mma8(float* d, unsigned a0, unsigned a1, unsigned a2, unsigned a3,
                                     unsigned b0, unsigned b1)
{
    asm("mma.sync.aligned.m16n8k8.row.col.f32.tf32.tf32.f32 "
        "{%0,%1,%2,%3}, {%4,%5,%6,%7}, {%8,%9}, {%0,%1,%2,%3};\n"
        : "+f"(d[0]), "+f"(d[1]), "+f"(d[2]), "+f"(d[3])
        : "r"(a0), "r"(a1), "r"(a2), "r"(a3), "r"(b0), "r"(b1));
}

__device__ __forceinline__ void split_tf32(float v, float& hi, float& lo)
{
    hi = __uint_as_float(__float_as_uint(v) & 0xFFFFE000u);
    float l = v - hi;
    lo = __uint_as_float(__float_as_uint(l) & 0xFFFFE000u);
}

// ---------------- split-tf32 tensor-core GEMM with register prefetch ----------------
// DUAL=false: C[M,N] = A @ B[K,N].  DUAL=true: N=128, cols 0-63 from B->C, 64-127 from B2->C2
// (per-matrix row stride 64), bias/bias2 per half, epi=1 semantics.
template <bool DUAL>
__global__ void __launch_bounds__(256)
sgemm_tc(const float* __restrict__ A, const float* __restrict__ B,
         const float* __restrict__ bias, float* __restrict__ C,
         int M, int N, int K, int epi,
         const float* __restrict__ B2, const float* __restrict__ bias2,
         float* __restrict__ C2)
{
    __shared__ float As[128 * PDS];
    __shared__ float Bs[128 * PDS];
    const int tid = threadIdx.x;
    const int wid = tid >> 5, lane = tid & 31;
    const int wm = wid & 1, wn = wid >> 1;
    const int grp = lane >> 2, tig = lane & 3;
    const int rb = blockIdx.y * 128, cb = blockIdx.x * 128;
    const int KT = K >> 4;

    float acc[4][4][4];
#pragma unroll
    for (int mt = 0; mt < 4; mt++)
#pragma unroll
        for (int nt = 0; nt < 4; nt++)
#pragma unroll
            for (int q = 0; q < 4; q++) acc[mt][nt][q] = 0.f;

    float4 va[2], vb[2];

    // prefetch tile 0
#pragma unroll
    for (int l = 0; l < 2; l++) {
        int idx = tid + l * 256;
        {
            int row = idx >> 2, q = idx & 3;
            int gm = rb + row;
            va[l] = make_float4(0.f, 0.f, 0.f, 0.f);
            if (gm < M) va[l] = *(const float4*)(A + (size_t)gm * K + q * 4);
        }
        {
            int kb = idx & 15, n4 = idx >> 4;
            int gn = cb + n4 * 4;
            vb[l] = make_float4(0.f, 0.f, 0.f, 0.f);
            if (DUAL) {
                const float* Bp = (n4 < 16) ? B : B2;
                int gn2 = (n4 < 16) ? gn : gn - 64;
                vb[l] = *(const float4*)(Bp + (size_t)kb * 64 + gn2);
            } else {
                if (gn + 3 < N) vb[l] = *(const float4*)(B + (size_t)kb * N + gn);
                else if (gn < N) {
                    vb[l].x = B[(size_t)kb * N + gn];
                    if (gn + 1 < N) vb[l].y = B[(size_t)kb * N + gn + 1];
                    if (gn + 2 < N) vb[l].z = B[(size_t)kb * N + gn + 2];
                }
            }
        }
    }

    for (int kt = 0; kt < KT; kt++) {
        // store prefetched tile into smem (split into hi/lo)
#pragma unroll
        for (int l = 0; l < 2; l++) {
            int idx = tid + l * 256;
            {
                int row = idx >> 2, q = idx & 3;
                float* dp = &As[row * PDS + q * 8];
                split_tf32(va[l].x, dp[0], dp[1]);
                split_tf32(va[l].y, dp[2], dp[3]);
                split_tf32(va[l].z, dp[4], dp[5]);
                split_tf32(va[l].w, dp[6], dp[7]);
            }
            {
                int kb = idx & 15, n4 = idx >> 4;
                float hi, lo;
                split_tf32(vb[l].x, hi, lo);
                Bs[(n4 * 4 + 0) * PDS + kb * 2] = hi; Bs[(n4 * 4 + 0) * PDS + kb * 2 + 1] = lo;
                split_tf32(vb[l].y, hi, lo);
                Bs[(n4 * 4 + 1) * PDS + kb * 2] = hi; Bs[(n4 * 4 + 1) * PDS + kb * 2 + 1] = lo;
                split_tf32(vb[l].z, hi, lo);
                Bs[(n4 * 4 + 2) * PDS + kb * 2] = hi; Bs[(n4 * 4 + 2) * PDS + kb * 2 + 1] = lo;
                split_tf32(vb[l].w, hi, lo);
                Bs[(n4 * 4 + 3) * PDS + kb * 2] = hi; Bs[(n4 * 4 + 3) * PDS + kb * 2 + 1] = lo;
            }
        }
        __syncthreads();

        // prefetch next tile
        if (kt + 1 < KT) {
            int k0 = (kt + 1) * 16;
#pragma unroll
            for (int l = 0; l < 2; l++) {
                int idx = tid + l * 256;
                {
                    int row = idx >> 2, q = idx & 3;
                    int gm = rb + row;
                    va[l] = make_float4(0.f, 0.f, 0.f, 0.f);
                    if (gm < M) va[l] = *(const float4*)(A + (size_t)gm * K + k0 + q * 4);
                }
                {
                    int kb = idx & 15, n4 = idx >> 4;
                    int gn = cb + n4 * 4;
                    vb[l] = make_float4(0.f, 0.f, 0.f, 0.f);
                    if (DUAL) {
                        const float* Bp = (n4 < 16) ? B : B2;
                        int gn2 = (n4 < 16) ? gn : gn - 64;
                        vb[l] = *(const float4*)(Bp + (size_t)(k0 + kb) * 64 + gn2);
                    } else {
                        if (gn + 3 < N) vb[l] = *(const float4*)(B + (size_t)(k0 + kb) * N + gn);
                        else if (gn < N) {
                            vb[l].x = B[(size_t)(k0 + kb) * N + gn];
                            if (gn + 1 < N) vb[l].y = B[(size_t)(k0 + kb) * N + gn + 1];
                            if (gn + 2 < N) vb[l].z = B[(size_t)(k0 + kb) * N + gn + 2];
                        }
                    }
                }
            }
        }

#pragma unroll
        for (int kc = 0; kc < 16; kc += 8) {
            unsigned ahi[4][4], alo[4][4];
#pragma unroll
            for (int mt = 0; mt < 4; mt++) {
                int r0 = (wm * 64 + mt * 16 + grp) * PDS + (kc + tig) * 2;
                int r1 = r0 + 8 * PDS;
                float2 p0 = *(const float2*)&As[r0];
                float2 p1 = *(const float2*)&As[r1];
                float2 p2 = *(const float2*)&As[r0 + 8];
                float2 p3 = *(const float2*)&As[r1 + 8];
                ahi[mt][0] = __float_as_uint(p0.x); alo[mt][0] = __float_as_uint(p0.y);
                ahi[mt][1] = __float_as_uint(p1.x); alo[mt][1] = __float_as_uint(p1.y);
                ahi[mt][2] = __float_as_uint(p2.x); alo[mt][2] = __float_as_uint(p2.y);
                ahi[mt][3] = __float_as_uint(p3.x); alo[mt][3] = __float_as_uint(p3.y);
            }
            unsigned bhi[4][2], blo[4][2];
#pragma unroll
            for (int nt = 0; nt < 4; nt++) {
                int rn = (wn * 32 + nt * 8 + grp) * PDS + (kc + tig) * 2;
                float2 q0 = *(const float2*)&Bs[rn];
                float2 q1 = *(const float2*)&Bs[rn + 8];
                bhi[nt][0] = __float_as_uint(q0.x); blo[nt][0] = __float_as_uint(q0.y);
                bhi[nt][1] = __float_as_uint(q1.x); blo[nt][1] = __float_as_uint(q1.y);
            }
#pragma unroll
            for (int mt = 0; mt < 4; mt++)
#pragma unroll
                for (int nt = 0; nt < 4; nt++) {
                    mma8(acc[mt][nt], ahi[mt][0], ahi[mt][1], ahi[mt][2], ahi[mt][3],
                         bhi[nt][0], bhi[nt][1]);
                    mma8(acc[mt][nt], ahi[mt][0], ahi[mt][1], ahi[mt][2], ahi[mt][3],
                         blo[nt][0], blo[nt][1]);
                    mma8(acc[mt][nt], alo[mt][0], alo[mt][1], alo[mt][2], alo[mt][3],
                         bhi[nt][0], bhi[nt][1]);
                }
        }
        __syncthreads();
    }

#pragma unroll
    for (int mt = 0; mt < 4; mt++) {
        int r0 = rb + wm * 64 + mt * 16 + grp;
        int r1 = r0 + 8;
#pragma unroll
        for (int nt = 0; nt < 4; nt++) {
            int c = cb + wn * 32 + nt * 8 + tig * 2;
            if (c >= N) continue;
            if (DUAL) {
                const float* bp = (c < 64) ? bias : bias2;
                float* Cp = (c < 64) ? C : C2;
                int cc = (c < 64) ? c : c - 64;
                float b0 = bp[cc], b1 = bp[cc + 1];
                if (r0 < M) *(float2*)&Cp[(size_t)r0 * 64 + cc] =
                    make_float2(acc[mt][nt][0] + b0, acc[mt][nt][1] + b1);
                if (r1 < M) *(float2*)&Cp[(size_t)r1 * 64 + cc] =
                    make_float2(acc[mt][nt][2] + b0, acc[mt][nt][3] + b1);
            } else {
                float b0 = 0.f, b1 = 0.f;
                if (epi >= 1) { b0 = bias[c]; b1 = bias[c + 1]; }
                if (r0 < M) {
                    float v0 = acc[mt][nt][0] + b0, v1 = acc[mt][nt][1] + b1;
                    if (epi == 2) { v0 = fmaxf(v0, 0.f); v1 = fmaxf(v1, 0.f); }
                    *(float2*)&C[(size_t)r0 * N + c] = make_float2(v0, v1);
                }
                if (r1 < M) {
                    float v0 = acc[mt][nt][2] + b0, v1 = acc[mt][nt][3] + b1;
                    if (epi == 2) { v0 = fmaxf(v0, 0.f); v1 = fmaxf(v1, 0.f); }
                    *(float2*)&C[(size_t)r1 * N + c] = make_float2(v0, v1);
                }
            }
        }
    }
}

// ---------------- attention projections ----------------
template <int C, int HC>
__global__ void attn_proj(const float* __restrict__ h, const float* __restrict__ as_,
                          const float* __restrict__ ad_)
{
    int n = blockIdx.x;
    int head = threadIdx.x >> 5, lane = threadIdx.x & 31;
    const float* hp = h + (size_t)n * HC + head * C;
    const float* sp = as_ + head * C;
    const float* dp = ad_ + head * C;
    float ss = 0.f, sd = 0.f;
#pragma unroll
    for (int c = lane; c < C; c += 32) {
        float v = hp[c];
        ss += v * sp[c];
        sd += v * dp[c];
    }
#pragma unroll
    for (int o = 16; o; o >>= 1) {
        ss += __shfl_xor_sync(0xffffffffu, ss, o);
        sd += __shfl_xor_sync(0xffffffffu, sd, o);
    }
    if (lane == 0) { g_al[n * 4 + head] = ss; g_ar[n * 4 + head] = sd; }
}

// ---------------- CSR build ----------------
__global__ void zero_cnt()
{
    int t = blockIdx.x * blockDim.x + threadIdx.x;
    if (t < NN) g_cnt[t] = 0;
}

__global__ void count_k(const int* __restrict__ dst, int E)
{
    int i = blockIdx.x * blockDim.x + threadIdx.x;
    if (i >= E + NN) return;
    int d = (i < E) ? dst[i] : (i - E);
    atomicAdd(&g_cnt[d], 1);
}

__global__ void scan_k()
{
    __shared__ int wsum[32];
    const int PER = 10;
    int tid = threadIdx.x;
    int lane = tid & 31, wid = tid >> 5;
    int base = tid * PER;
    int v[PER];
    int s = 0;
#pragma unroll
    for (int q = 0; q < PER; q++) {
        int i = base + q;
        v[q] = (i < NN) ? g_cnt[i] : 0;
        s += v[q];
    }
    int t = s;
#pragma unroll
    for (int o = 1; o < 32; o <<= 1) {
        int u = __shfl_up_sync(0xffffffffu, t, o);
        if (lane >= o) t += u;
    }
    if (lane == 31) wsum[wid] = t;
    __syncthreads();
    if (wid == 0) {
        int w = wsum[lane];
#pragma unroll
        for (int o = 1; o < 32; o <<= 1) {
            int u = __shfl_up_sync(0xffffffffu, w, o);
            if (lane >= o) w += u;
        }
        wsum[lane] = w;
    }
    __syncthreads();
    int excl = t - s + ((wid > 0) ? wsum[wid - 1] : 0);
#pragma unroll
    for (int q = 0; q < PER; q++) {
        int i = base + q;
        if (i < NN) { g_off[i] = excl; g_cnt[i] = excl; }
        excl += v[q];
    }
    if (tid == 1023) g_off[NN] = excl;
}

__global__ void scatter_k(const int* __restrict__ dst, int E)
{
    int i = blockIdx.x * blockDim.x + threadIdx.x;
    if (i >= E + NN) return;
    int d = (i < E) ? dst[i] : (i - E);
    int pos = atomicAdd(&g_cnt[d], 1);
    g_perm[pos] = i;
}

// ---------------- fused GAT aggregation ----------------
template <int C, int HC, int RELU>
__global__ void gat_agg(const int* __restrict__ src, int E,
                        const float* __restrict__ h,
                        const float* __restrict__ bias,
                        float* __restrict__ out)
{
    constexpr int ACC = C / 128;
    __shared__ int    sm_s[128];
    __shared__ float4 sm_w[128];
    __shared__ float4 sred[4];

    int n = blockIdx.x;
    int tid = threadIdx.x;
    int wid = tid >> 5, lane = tid & 31;
    int head = wid;
    int slot = lane;
    int off = g_off[n];
    int deg = g_off[n + 1] - off;

    float4 arn = *(const float4*)&g_ar[n * 4];

    float4 mx = make_float4(-1e30f, -1e30f, -1e30f, -1e30f);
    for (int j = tid; j < deg; j += 128) {
        int e = g_perm[off + j];
        int s = (e < E) ? src[e] : (e - E);
        float4 a = *(const float4*)&g_al[s * 4];
        float l0 = a.x + arn.x; l0 = l0 >= 0.f ? l0 : 0.2f * l0;
        float l1 = a.y + arn.y; l1 = l1 >= 0.f ? l1 : 0.2f * l1;
        float l2 = a.z + arn.z; l2 = l2 >= 0.f ? l2 : 0.2f * l2;
        float l3 = a.w + arn.w; l3 = l3 >= 0.f ? l3 : 0.2f * l3;
        mx.x = fmaxf(mx.x, l0); mx.y = fmaxf(mx.y, l1);
        mx.z = fmaxf(mx.z, l2); mx.w = fmaxf(mx.w, l3);
    }
#pragma unroll
    for (int o = 16; o; o >>= 1) {
        mx.x = fmaxf(mx.x, __shfl_xor_sync(0xffffffffu, mx.x, o));
        mx.y = fmaxf(mx.y, __shfl_xor_sync(0xffffffffu, mx.y, o));
        mx.z = fmaxf(mx.z, __shfl_xor_sync(0xffffffffu, mx.z, o));
        mx.w = fmaxf(mx.w, __shfl_xor_sync(0xffffffffu, mx.w, o));
    }
    if (lane == 0) sred[wid] = mx;
    __syncthreads();
    if (tid == 0) {
        float4 a = sred[0];
#pragma unroll
        for (int w = 1; w < 4; w++) {
            float4 b = sred[w];
            a.x = fmaxf(a.x, b.x); a.y = fmaxf(a.y, b.y);
            a.z = fmaxf(a.z, b.z); a.w = fmaxf(a.w, b.w);
        }
        sred[0] = a;
    }
    __syncthreads();
    mx = sred[0];
    __syncthreads();

    float4 acc[ACC];
#pragma unroll
    for (int q = 0; q < ACC; q++) acc[q] = make_float4(0.f, 0.f, 0.f, 0.f);
    float4 den = make_float4(0.f, 0.f, 0.f, 0.f);
    const float* sm_wf = (const float*)sm_w;

    for (int base = 0; base < deg; base += 128) {
        int cnt = min(128, deg - base);
        int j = base + tid;
        if (j < deg) {
            int e = g_perm[off + j];
            int s = (e < E) ? src[e] : (e - E);
            float4 a = *(const float4*)&g_al[s * 4];
            float l0 = a.x + arn.x; l0 = l0 >= 0.f ? l0 : 0.2f * l0;
            float l1 = a.y + arn.y; l1 = l1 >= 0.f ? l1 : 0.2f * l1;
            float l2 = a.z + arn.z; l2 = l2 >= 0.f ? l2 : 0.2f * l2;
            float l3 = a.w + arn.w; l3 = l3 >= 0.f ? l3 : 0.2f * l3;
            float4 ex = make_float4(expf(l0 - mx.x), expf(l1 - mx.y),
                                    expf(l2 - mx.z), expf(l3 - mx.w));
            den.x += ex.x; den.y += ex.y; den.z += ex.z; den.w += ex.w;
            sm_s[tid] = s;
            sm_w[tid] = ex;
        }
        __syncthreads();
#pragma unroll 4
        for (int j2 = 0; j2 < cnt; j2++) {
            int s = sm_s[j2];
            float w = sm_wf[j2 * 4 + head];
            const float4* hs = (const float4*)(h + (size_t)s * HC + head * C);
#pragma unroll
            for (int q = 0; q < ACC; q++) {
                float4 v = hs[slot + q * 32];
                acc[q].x += w * v.x; acc[q].y += w * v.y;
                acc[q].z += w * v.z; acc[q].w += w * v.w;
            }
        }
        __syncthreads();
    }

#pragma unroll
    for (int o = 16; o; o >>= 1) {
        den.x += __shfl_xor_sync(0xffffffffu, den.x, o);
        den.y += __shfl_xor_sync(0xffffffffu, den.y, o);
        den.z += __shfl_xor_sync(0xffffffffu, den.z, o);
        den.w += __shfl_xor_sync(0xffffffffu, den.w, o);
    }
    if (lane == 0) sred[wid] = den;
    __syncthreads();
    if (tid == 0) {
        float4 a = sred[0];
#pragma unroll
        for (int w = 1; w < 4; w++) {
            float4 b = sred[w];
            a.x += b.x; a.y += b.y; a.z += b.z; a.w += b.w;
        }
        sred[0] = a;
    }
    __syncthreads();
    den = sred[0];
    float d4[4];
    *(float4*)d4 = den;
    float mi = 1.0f / (4.0f * d4[head]);

    float4* sm_acc = sm_w;
#pragma unroll
    for (int q = 0; q < ACC; q++) {
        __syncthreads();
        float4 a = acc[q];
        a.x *= mi; a.y *= mi; a.z *= mi; a.w *= mi;
        sm_acc[tid] = a;
        __syncthreads();
        if (tid < 32) {
            float4 a0 = sm_acc[tid], a1 = sm_acc[tid + 32];
            float4 a2 = sm_acc[tid + 64], a3 = sm_acc[tid + 96];
            int c4 = tid + q * 32;
            float4 b = ((const float4*)bias)[c4];
            float4 v;
            v.x = a0.x + a1.x + a2.x + a3.x + b.x;
            v.y = a0.y + a1.y + a2.y + a3.y + b.y;
            v.z = a0.z + a1.z + a2.z + a3.z + b.z;
            v.w = a0.w + a1.w + a2.w + a3.w + b.w;
            if (RELU) {
                v.x = fmaxf(v.x, 0.f); v.y = fmaxf(v.y, 0.f);
                v.z = fmaxf(v.z, 0.f); v.w = fmaxf(v.w, 0.f);
            }
            ((float4*)(out + (size_t)n * C))[c4] = v;
        }
    }
}

// ---------------- reparameterize ----------------
__device__ __forceinline__ unsigned rotl32(unsigned x, int d) { return (x << d) | (x >> (32 - d)); }

__device__ __forceinline__ float bits_to_normal(unsigned bits) {
    float f = __uint_as_float((bits >> 9) | 0x3f800000u) - 1.0f;
    const float lo = -0.99999994f;
    float u = fmaxf(lo, f * (1.0f - lo) + lo);
    return 1.41421356237f * erfinvf(u);
}

__global__ void reparam(const float* __restrict__ mu, const float* __restrict__ lv,
                        float* __restrict__ z, int n)
{
    int i = blockIdx.x * blockDim.x + threadIdx.x;
    if (i >= n) return;
    const unsigned ks0 = 0u, ks1 = 1u, ks2 = 0x1BD11BDBu;
    unsigned x0 = 0u + ks0;
    unsigned x1 = (unsigned)i + ks1;
#define TFR(r) { x0 += x1; x1 = rotl32(x1, r); x1 ^= x0; }
    TFR(13) TFR(15) TFR(26) TFR(6)
    x0 += ks1; x1 += ks2 + 1u;
    TFR(17) TFR(29) TFR(16) TFR(24)
    x0 += ks2; x1 += ks0 + 2u;
    TFR(13) TFR(15) TFR(26) TFR(6)
    x0 += ks0; x1 += ks1 + 3u;
    TFR(17) TFR(29) TFR(16) TFR(24)
    x0 += ks1; x1 += ks2 + 4u;
    TFR(13) TFR(15) TFR(26) TFR(6)
    x0 += ks2; x1 += ks0 + 5u;
#undef TFR
    float eps = bits_to_normal(x0 ^ x1);
    z[i] = mu[i] + eps * expf(0.5f * lv[i]);
}

// ---------------- pd prep: row norms + tf32 hi/lo split ----------------
__global__ void rownorm_split(const float* __restrict__ r,
                              float* __restrict__ phi, float* __restrict__ plo)
{
    int row = (blockIdx.x * blockDim.x + threadIdx.x) >> 5;
    int lane = threadIdx.x & 31;
    if (row >= NN) return;
    float s = 0.f;
#pragma unroll
    for (int c = lane; c < 128; c += 32) {
        float v = r[(size_t)row * 128 + c];
        s += v * v;
        float hi, lo;
        split_tf32(v, hi, lo);
        phi[(size_t)row * 128 + c] = hi;
        plo[(size_t)row * 128 + c] = lo;
    }
#pragma unroll
    for (int o = 16; o; o >>= 1) s += __shfl_xor_sync(0xffffffffu, s, o);
    if (lane == 0) g_sq[row] = s;
}

// ---------------- pd via tf32 split mma, upper-triangle + mirror, reg prefetch ----------------
#define TRS 132

__global__ void __launch_bounds__(256)
pd_tc(const float* __restrict__ Rhi, const float* __restrict__ Rlo,
      float* __restrict__ P)
{
    const int bx = blockIdx.x, by = blockIdx.y;
    if (by > bx) return;
    __shared__ float sm[10240];
    float* As = sm;
    float* Bs = sm + 5120;
    const int tid = threadIdx.x;
    const int wid = tid >> 5, lane = tid & 31;
    const int wm = wid & 1, wn = wid >> 1;
    const int grp = lane >> 2, tig = lane & 3;
    const int rb = by * 128, cb = bx * 128;

    float acc[4][4][4];
#pragma unroll
    for (int mt = 0; mt < 4; mt++)
#pragma unroll
        for (int nt = 0; nt < 4; nt++)
#pragma unroll
            for (int q = 0; q < 4; q++) acc[mt][nt][q] = 0.f;

    float4 vah[2], val_[2], vbh[2], vbl[2];

    // prefetch kt=0
#pragma unroll
    for (int l = 0; l < 2; l++) {
        int idx = tid + l * 256;
        int row = idx >> 2, q = idx & 3;
        int gr = rb + row, gc = cb + row;
        vah[l] = make_float4(0.f, 0.f, 0.f, 0.f); val_[l] = vah[l];
        vbh[l] = vah[l]; vbl[l] = vah[l];
        if (gr < NN) {
            vah[l]  = *(const float4*)&Rhi[(size_t)gr * 128 + q * 4];
            val_[l] = *(const float4*)&Rlo[(size_t)gr * 128 + q * 4];
        }
        if (gc < NN) {
            vbh[l] = *(const float4*)&Rhi[(size_t)gc * 128 + q * 4];
            vbl[l] = *(const float4*)&Rlo[(size_t)gc * 128 + q * 4];
        }
    }

    for (int kt = 0; kt < 8; kt++) {
#pragma unroll
        for (int l = 0; l < 2; l++) {
            int idx = tid + l * 256;
            int row = idx >> 2, q = idx & 3;
            float* dp = &As[row * PDS + q * 8];
            dp[0] = vah[l].x; dp[1] = val_[l].x; dp[2] = vah[l].y; dp[3] = val_[l].y;
            dp[4] = vah[l].z; dp[5] = val_[l].z; dp[6] = vah[l].w; dp[7] = val_[l].w;
            dp = &Bs[row * PDS + q * 8];
            dp[0] = vbh[l].x; dp[1] = vbl[l].x; dp[2] = vbh[l].y; dp[3] = vbl[l].y;
            dp[4] = vbh[l].z; dp[5] = vbl[l].z; dp[6] = vbh[l].w; dp[7] = vbl[l].w;
        }
        __syncthreads();

        if (kt + 1 < 8) {
            int k0 = (kt + 1) * 16;
#pragma unroll
            for (int l = 0; l < 2; l++) {
                int idx = tid + l * 256;
                int row = idx >> 2, q = idx & 3;
                int gr = rb + row, gc = cb + row;
                vah[l] = make_float4(0.f, 0.f, 0.f, 0.f); val_[l] = vah[l];
                vbh[l] = vah[l]; vbl[l] = vah[l];
                if (gr < NN) {
                    vah[l]  = *(const float4*)&Rhi[(size_t)gr * 128 + k0 + q * 4];
                    val_[l] = *(const float4*)&Rlo[(size_t)gr * 128 + k0 + q * 4];
                }
                if (gc < NN) {
                    vbh[l] = *(const float4*)&Rhi[(size_t)gc * 128 + k0 + q * 4];
                    vbl[l] = *(const float4*)&Rlo[(size_t)gc * 128 + k0 + q * 4];
                }
            }
        }

#pragma unroll
        for (int kc = 0; kc < 16; kc += 8) {
            unsigned ahi[4][4], alo[4][4];
#pragma unroll
            for (int mt = 0; mt < 4; mt++) {
                int r0 = (wm * 64 + mt * 16 + grp) * PDS + (kc + tig) * 2;
                int r1 = r0 + 8 * PDS;
                float2 p0 = *(const float2*)&As[r0];
                float2 p1 = *(const float2*)&As[r1];
                float2 p2 = *(const float2*)&As[r0 + 8];
                float2 p3 = *(const float2*)&As[r1 + 8];
                ahi[mt][0] = __float_as_uint(p0.x); alo[mt][0] = __float_as_uint(p0.y);
                ahi[mt][1] = __float_as_uint(p1.x); alo[mt][1] = __float_as_uint(p1.y);
                ahi[mt][2] = __float_as_uint(p2.x); alo[mt][2] = __float_as_uint(p2.y);
                ahi[mt][3] = __float_as_uint(p3.x); alo[mt][3] = __float_as_uint(p3.y);
            }
            unsigned bhi[4][2], blo[4][2];
#pragma unroll
            for (int nt = 0; nt < 4; nt++) {
                int rn = (wn * 32 + nt * 8 + grp) * PDS + (kc + tig) * 2;
                float2 q0 = *(const float2*)&Bs[rn];
                float2 q1 = *(const float2*)&Bs[rn + 8];
                bhi[nt][0] = __float_as_uint(q0.x); blo[nt][0] = __float_as_uint(q0.y);
                bhi[nt][1] = __float_as_uint(q1.x); blo[nt][1] = __float_as_uint(q1.y);
            }
#pragma unroll
            for (int mt = 0; mt < 4; mt++)
#pragma unroll
                for (int nt = 0; nt < 4; nt++) {
                    mma8(acc[mt][nt], ahi[mt][0], ahi[mt][1], ahi[mt][2], ahi[mt][3],
                         bhi[nt][0], bhi[nt][1]);
                    mma8(acc[mt][nt], ahi[mt][0], ahi[mt][1], ahi[mt][2], ahi[mt][3],
                         blo[nt][0], blo[nt][1]);
                    mma8(acc[mt][nt], alo[mt][0], alo[mt][1], alo[mt][2], alo[mt][3],
                         bhi[nt][0], bhi[nt][1]);
                }
        }
        __syncthreads();
    }

    // acc -> distances
#pragma unroll
    for (int mt = 0; mt < 4; mt++) {
        int r0 = rb + wm * 64 + mt * 16 + grp;
        int r1 = r0 + 8;
        float sq0 = (r0 < NN) ? g_sq[r0] : 0.f;
        float sq1 = (r1 < NN) ? g_sq[r1] : 0.f;
#pragma unroll
        for (int nt = 0; nt < 4; nt++) {
            int c = cb + wn * 32 + nt * 8 + tig * 2;
            float sc0 = (c < NN) ? g_sq[c] : 0.f;
            float sc1 = (c + 1 < NN) ? g_sq[c + 1] : 0.f;
            acc[mt][nt][0] = sqrtf(fmaxf(sq0 + sc0 - 2.f * acc[mt][nt][0], 1e-12f));
            acc[mt][nt][1] = sqrtf(fmaxf(sq0 + sc1 - 2.f * acc[mt][nt][1], 1e-12f));
            acc[mt][nt][2] = sqrtf(fmaxf(sq1 + sc0 - 2.f * acc[mt][nt][2], 1e-12f));
            acc[mt][nt][3] = sqrtf(fmaxf(sq1 + sc1 - 2.f * acc[mt][nt][3], 1e-12f));
        }
    }

    // direct (upper) write
#pragma unroll
    for (int mt = 0; mt < 4; mt++) {
        int r0 = rb + wm * 64 + mt * 16 + grp;
        int r1 = r0 + 8;
#pragma unroll
        for (int nt = 0; nt < 4; nt++) {
            int c = cb + wn * 32 + nt * 8 + tig * 2;
            if (c + 1 < NN) {
                if (r0 < NN) *(float2*)&P[(size_t)r0 * NN + c] =
                    make_float2(acc[mt][nt][0], acc[mt][nt][1]);
                if (r1 < NN) *(float2*)&P[(size_t)r1 * NN + c] =
                    make_float2(acc[mt][nt][2], acc[mt][nt][3]);
            } else if (c < NN) {
                if (r0 < NN) P[(size_t)r0 * NN + c] = acc[mt][nt][0];
                if (r1 < NN) P[(size_t)r1 * NN + c] = acc[mt][nt][2];
            }
        }
    }

    // mirrored (lower) write via smem transpose
    if (bx != by) {
        float (*T)[TRS] = (float(*)[TRS])sm;
#pragma unroll
        for (int half = 0; half < 2; half++) {
            __syncthreads();
            if ((wn >> 1) == half) {
#pragma unroll
                for (int mt = 0; mt < 4; mt++) {
                    int r0l = wm * 64 + mt * 16 + grp;
                    int r1l = r0l + 8;
#pragma unroll
                    for (int nt = 0; nt < 4; nt++) {
                        int cl = wn * 32 + nt * 8 + tig * 2 - half * 64;
                        T[cl][r0l]     = acc[mt][nt][0];
                        T[cl + 1][r0l] = acc[mt][nt][1];
                        T[cl][r1l]     = acc[mt][nt][2];
                        T[cl + 1][r1l] = acc[mt][nt][3];
                    }
                }
            }
            __syncthreads();
            int row = tid >> 2, q = tid & 3;
            int c = cb + half * 64 + row;
            if (c < NN) {
#pragma unroll
                for (int k = 0; k < 8; k++) {
                    int r = rb + q * 32 + k * 4;
                    if (r < NN) {
                        float4 v = make_float4(T[row][q * 32 + k * 4 + 0],
                                               T[row][q * 32 + k * 4 + 1],
                                               T[row][q * 32 + k * 4 + 2],
                                               T[row][q * 32 + k * 4 + 3]);
                        *(float4*)&P[(size_t)c * NN + r] = v;
                    }
                }
            }
        }
    }
}

// ---------------- launch ----------------
static inline int divup(int a, int b) { return (a + b - 1) / b; }

extern "C" void kernel_launch(void* const* d_in, const int* in_sizes, int n_in,
                              void* d_out, int out_size)
{
    const float* x   = (const float*)d_in[0];
    const int*   ei  = (const int*)d_in[1];
    const int E = in_sizes[1] / 2;
    const float* W1  = (const float*)d_in[2];
    const float* a1s = (const float*)d_in[3];
    const float* a1d = (const float*)d_in[4];
    const float* b1  = (const float*)d_in[5];
    const float* W2  = (const float*)d_in[6];
    const float* a2s = (const float*)d_in[7];
    const float* a2d = (const float*)d_in[8];
    const float* b2  = (const float*)d_in[9];
    const float* Wmu = (const float*)d_in[10];
    const float* bmu = (const float*)d_in[11];
    const float* Wlv = (const float*)d_in[12];
    const float* blv = (const float*)d_in[13];
    const float* Wd1 = (const float*)d_in[14];
    const float* bd1 = (const float*)d_in[15];
    const float* Wd2 = (const float*)d_in[16];
    const float* bd2 = (const float*)d_in[17];
    const float* W3  = (const float*)d_in[18];
    const float* a3s = (const float*)d_in[19];
    const float* a3d = (const float*)d_in[20];
    const float* b3  = (const float*)d_in[21];

    float* out     = (float*)d_out;
    float* d_recon = out;
    float* d_mu    = out + (size_t)NN * 128;
    float* d_lv    = d_mu + (size_t)NN * 64;
    float* d_pd    = d_lv + (size_t)NN * 64;

    float *hbuf, *out1, *out2, *zb, *d1b, *d2b;
    cudaGetSymbolAddress((void**)&hbuf, g_hbuf);
    cudaGetSymbolAddress((void**)&out1, g_out1);
    cudaGetSymbolAddress((void**)&out2, g_out2);
    cudaGetSymbolAddress((void**)&zb,   g_zb);
    cudaGetSymbolAddress((void**)&d1b,  g_d1b);
    cudaGetSymbolAddress((void**)&d2b,  g_d2b);

    const int* srcp = ei;
    const int* dstp = ei + E;
    const int ET = E + NN;
    const int EB = divup(ET, 256);

    // CSR (first 3) then conv1 GEMM as launch #4 (ncu capture target), then rest
    zero_cnt<<<divup(NN, 256), 256>>>();
    count_k<<<EB, 256>>>(dstp, E);
    scan_k<<<1, 1024>>>();
    sgemm_tc<false><<<dim3(8, 79), 256>>>(x, W1, nullptr, hbuf, NN, 1024, 128, 0,
                                          nullptr, nullptr, nullptr);
    scatter_k<<<EB, 256>>>(dstp, E);
    attn_proj<256, 1024><<<NN, 128>>>(hbuf, a1s, a1d);
    gat_agg<256, 1024, 1><<<NN, 128>>>(srcp, E, hbuf, b1, out1);

    // ----- encoder conv2 -----
    sgemm_tc<false><<<dim3(4, 79), 256>>>(out1, W2, nullptr, hbuf, NN, 512, 256, 0,
                                          nullptr, nullptr, nullptr);
    attn_proj<128, 512><<<NN, 128>>>(hbuf, a2s, a2d);
    gat_agg<128, 512, 1><<<NN, 128>>>(srcp, E, hbuf, b2, out2);

    // ----- mu / logvar heads (merged dual GEMM) -----
    sgemm_tc<true><<<dim3(1, 79), 256>>>(out2, Wmu, bmu, d_mu, NN, 128, 128, 1,
                                         Wlv, blv, d_lv);

    // ----- reparameterize -----
    reparam<<<divup(NN * 64, 256), 256>>>(d_mu, d_lv, zb, NN * 64);

    // ----- decoder dense -----
    sgemm_tc<false><<<dim3(1, 79), 256>>>(zb,  Wd1, bd1, d1b, NN, 128, 64, 2,
                                          nullptr, nullptr, nullptr);
    sgemm_tc<false><<<dim3(2, 79), 256>>>(d1b, Wd2, bd2, d2b, NN, 256, 128, 2,
                                          nullptr, nullptr, nullptr);

    // ----- decoder conv3 -----
    sgemm_tc<false><<<dim3(4, 79), 256>>>(d2b, W3, nullptr, hbuf, NN, 512, 256, 0,
                                          nullptr, nullptr, nullptr);
    attn_proj<128, 512><<<NN, 128>>>(hbuf, a3s, a3d);
    gat_agg<128, 512, 0><<<NN, 128>>>(srcp, E, hbuf, b3, d_recon);

    // ----- pairwise distances -----
    float* phi = hbuf;
    float* plo = hbuf + (size_t)NN * 128;
    rownorm_split<<<divup(NN * 32, 256), 256>>>(d_recon, phi, plo);
    pd_tc<<<dim3(79, 79), 256>>>(phi, plo, d_pd);
}